// round 15
// baseline (speedup 1.0000x reference)
#include <cuda_runtime.h>
#include <cuda_bf16.h>
#include <cstdint>

static const int HWX = 65536;   // 256*256
static const int WD  = 256;
static const int CH  = 64;

// ---------------------------------------------------------------------------
// Scratch: everything pre-split into bf16 hi/lo, straight and transposed.
// ---------------------------------------------------------------------------
__device__ __nv_bfloat16 g_qh[16777216],  g_ql[16777216];
__device__ __nv_bfloat16 g_vh[16777216],  g_vl[16777216];
__device__ __nv_bfloat16 g_kh[67108864],  g_kl[67108864];
__device__ __nv_bfloat16 g_qth[16777216], g_qtl[16777216];
__device__ __nv_bfloat16 g_vth[16777216], g_vtl[16777216];
__device__ __nv_bfloat16 g_kth[67108864], g_ktl[67108864];
__device__ __nv_bfloat16 g_psh[16777216], g_psl[16777216];  // sum_n P_space, TRANSPOSED [v][w]

// ---------------------------------------------------------------------------
// SMEM layout (attention). PITCH 144 B per 64-k row -> conflict-free ldmatrix.
// ---------------------------------------------------------------------------
static const int PITCH   = 144;
static const int A_CHUNK = 64 * PITCH;              // 9216
static const int SM_AH   = 0;                       // 4*9216 = 36864
static const int SM_AL   = 36864;
static const int B_PLANE = 256 * PITCH;             // 36864
static const int SM_B0H  = 73728;
static const int SM_B0L  = SM_B0H + B_PLANE;        // 110592
static const int SM_B1H  = SM_B0L + B_PLANE;        // 147456
static const int SM_B1L  = SM_B1H + B_PLANE;        // 184320
static const int SM_RS   = SM_B1L + B_PLANE;        // 221184 ([4][64] floats)
static const int SM_TOTAL = SM_RS + 1024;           // 222208

static const int TP_SMEM = 2 * 256 * 33 * 4;        // 67584 (transpose tile)

// ---------------------------------------------------------------------------
// Helpers
// ---------------------------------------------------------------------------
__device__ __forceinline__ uint32_t smem_u32(const void* p) {
  uint32_t a;
  asm("{ .reg .u64 t; cvta.to.shared.u64 t, %1; cvt.u32.u64 %0, t; }" : "=r"(a) : "l"(p));
  return a;
}
__device__ __forceinline__ void split2(float x0, float x1, uint32_t& hi2, uint32_t& lo2) {
  __nv_bfloat162 h = __floats2bfloat162_rn(x0, x1);
  float r0 = x0 - __bfloat162float(h.x);
  float r1 = x1 - __bfloat162float(h.y);
  __nv_bfloat162 l = __floats2bfloat162_rn(r0, r1);
  hi2 = *(uint32_t*)&h;
  lo2 = *(uint32_t*)&l;
}
__device__ __forceinline__ void split1(float x, __nv_bfloat16& h, __nv_bfloat16& l) {
  h = __float2bfloat16(x);
  l = __float2bfloat16(x - __bfloat162float(h));
}

__device__ __forceinline__ void mma16816(float c[4], uint32_t a0, uint32_t a1,
                                         uint32_t a2, uint32_t a3,
                                         uint32_t b0, uint32_t b1) {
  asm volatile(
    "mma.sync.aligned.m16n8k16.row.col.f32.bf16.bf16.f32 "
    "{%0,%1,%2,%3}, {%4,%5,%6,%7}, {%8,%9}, {%0,%1,%2,%3};"
    : "+f"(c[0]), "+f"(c[1]), "+f"(c[2]), "+f"(c[3])
    : "r"(a0), "r"(a1), "r"(a2), "r"(a3), "r"(b0), "r"(b1));
}
__device__ __forceinline__ void ldmx4(uint32_t& r0, uint32_t& r1, uint32_t& r2, uint32_t& r3,
                                      uint32_t addr) {
  asm volatile("ldmatrix.sync.aligned.m8n8.x4.shared.b16 {%0,%1,%2,%3}, [%4];"
               : "=r"(r0), "=r"(r1), "=r"(r2), "=r"(r3) : "r"(addr));
}

#define CP16(dst, src)  asm volatile("cp.async.cg.shared.global [%0], [%1], 16;" :: "r"(dst), "l"(src))
#define CP_COMMIT()     asm volatile("cp.async.commit_group;" ::: "memory")
#define CP_WAIT0()      asm volatile("cp.async.wait_group 0;" ::: "memory")

// A fill (all 4 k-chunks, 64 rows): strength-reduced pointer-marching copies.
__device__ __forceinline__ void cpa_A(uint32_t sb, const __nv_bfloat16* srcH,
                                      const __nv_bfloat16* srcL, size_t rowbase, int tid) {
  const int m0 = tid >> 5, s = tid & 31;
  const __nv_bfloat16* pH = srcH + rowbase + (size_t)m0 * WD + s * 8;
  const __nv_bfloat16* pL = srcL + rowbase + (size_t)m0 * WD + s * 8;
  const uint32_t off = (uint32_t)((s >> 3) * A_CHUNK + m0 * PITCH + (s & 7) * 16);
  uint32_t dh = sb + SM_AH + off, dl = sb + SM_AL + off;
#pragma unroll
  for (int j = 0; j < 8; j++) {
    CP16(dh, pH);
    CP16(dl, pL);
    pH += 8 * WD; pL += 8 * WD;
    dh += 8 * PITCH; dl += 8 * PITCH;
  }
}
// B fill (one 64-k chunk, 256 rows)
__device__ __forceinline__ void cpa_B(uint32_t sb, uint32_t dH, uint32_t dL,
                                      const __nv_bfloat16* srcH, const __nv_bfloat16* srcL,
                                      size_t base, int koff, int tid) {
  const int n0 = tid >> 3, s = tid & 7;
  const __nv_bfloat16* pH = srcH + base + (size_t)n0 * WD + koff + s * 8;
  const __nv_bfloat16* pL = srcL + base + (size_t)n0 * WD + koff + s * 8;
  uint32_t dh = sb + dH + (uint32_t)(n0 * PITCH + s * 16);
  uint32_t dl = sb + dL + (uint32_t)(n0 * PITCH + s * 16);
#pragma unroll
  for (int j = 0; j < 8; j++) {
    CP16(dh, pH);
    CP16(dl, pL);
    pH += 32 * WD; pL += 32 * WD;
    dh += 32 * PITCH; dl += 32 * PITCH;
  }
}

// ---------------------------------------------------------------------------
// One 64-k chunk: acc[2][8][4] += A_chunk * B^T  (3-term bf16 split)
// Warp tile 32(M) x 64(N): wm in {0,1}, wn in {0..3}. 8 warps.
// ---------------------------------------------------------------------------
__device__ __forceinline__ void gemm_chunk(uint32_t sb, int ac, uint32_t bufH, uint32_t bufL,
                                           int lane, int wm, int wn, float (&acc)[2][8][4]) {
  const int i8 = lane & 7, q = lane >> 3;
  uint32_t bAddr = sb + (q < 2 ? bufH : bufL) + (uint32_t)(wn * 64 + i8) * PITCH + (q & 1) * 16;
  const int i16 = lane & 15, hsel = lane >> 4;
  uint32_t aAddrH = sb + SM_AH + ac * A_CHUNK + (uint32_t)(wm * 32 + i16) * PITCH + hsel * 16;
  uint32_t aAddrL = aAddrH + (SM_AL - SM_AH);
#pragma unroll
  for (int kt = 0; kt < 4; kt++) {
    uint32_t h00, h01, h02, h03, h10, h11, h12, h13;
    uint32_t l00, l01, l02, l03, l10, l11, l12, l13;
    ldmx4(h00, h01, h02, h03, aAddrH + kt * 32);
    ldmx4(h10, h11, h12, h13, aAddrH + 16 * PITCH + kt * 32);
    ldmx4(l00, l01, l02, l03, aAddrL + kt * 32);
    ldmx4(l10, l11, l12, l13, aAddrL + 16 * PITCH + kt * 32);
#pragma unroll
    for (int nt = 0; nt < 8; nt++) {
      uint32_t b0, b1, b2, b3;  // bh0, bh1, bl0, bl1 in ONE ldmatrix
      ldmx4(b0, b1, b2, b3, bAddr + nt * 8 * PITCH + kt * 32);
      mma16816(acc[0][nt], h00, h01, h02, h03, b0, b1);
      mma16816(acc[1][nt], h10, h11, h12, h13, b0, b1);
      mma16816(acc[0][nt], l00, l01, l02, l03, b0, b1);
      mma16816(acc[1][nt], l10, l11, l12, l13, b0, b1);
      mma16816(acc[0][nt], h00, h01, h02, h03, b2, b3);
      mma16816(acc[1][nt], h10, h11, h12, h13, b2, b3);
    }
  }
}

__device__ __forceinline__ void zero_acc(float (&a)[2][8][4]) {
#pragma unroll
  for (int mi = 0; mi < 2; mi++)
#pragma unroll
    for (int nt = 0; nt < 8; nt++)
#pragma unroll
      for (int e = 0; e < 4; e++) a[mi][nt][e] = 0.f;
}

// softmax over full 256-wide rows (cols span the 4 wn warps), accumulate into P
__device__ __forceinline__ void softmax_acc(char* smem, float (&S)[2][8][4], float (&P)[2][8][4],
                                            int lane, int wm, int wn) {
  const int r = lane >> 2, t = lane & 3;
  float* rs = (float*)(smem + SM_RS);  // [4 wn][64 rows]
  float s[4] = {0.f, 0.f, 0.f, 0.f};
#pragma unroll
  for (int mi = 0; mi < 2; mi++)
#pragma unroll
    for (int nt = 0; nt < 8; nt++) {
#pragma unroll
      for (int e = 0; e < 4; e++) S[mi][nt][e] = __expf(S[mi][nt][e] * 0.0625f);
      s[mi * 2 + 0] += S[mi][nt][0] + S[mi][nt][1];
      s[mi * 2 + 1] += S[mi][nt][2] + S[mi][nt][3];
    }
#pragma unroll
  for (int o = 1; o <= 2; o <<= 1)
#pragma unroll
    for (int i = 0; i < 4; i++) s[i] += __shfl_xor_sync(0xffffffffu, s[i], o);
  if (t == 0) {
#pragma unroll
    for (int mi = 0; mi < 2; mi++) {
      rs[wn * 64 + wm * 32 + mi * 16 + r]     = s[mi * 2 + 0];
      rs[wn * 64 + wm * 32 + mi * 16 + r + 8] = s[mi * 2 + 1];
    }
  }
  __syncthreads();
#pragma unroll
  for (int mi = 0; mi < 2; mi++) {
    int row = wm * 32 + mi * 16 + r;
    float inv0 = 1.0f / (rs[row] + rs[64 + row] + rs[128 + row] + rs[192 + row]);
    float inv1 = 1.0f / (rs[row + 8] + rs[64 + row + 8] + rs[128 + row + 8] + rs[192 + row + 8]);
#pragma unroll
    for (int nt = 0; nt < 8; nt++) {
      P[mi][nt][0] += S[mi][nt][0] * inv0;
      P[mi][nt][1] += S[mi][nt][1] * inv0;
      P[mi][nt][2] += S[mi][nt][2] * inv1;
      P[mi][nt][3] += S[mi][nt][3] * inv1;
    }
  }
  __syncthreads();
}

// write P fragments into the A smem region (split, fragment-native layout)
__device__ __forceinline__ void store_P_to_A(char* smem, const float (&P)[2][8][4],
                                             int lane, int wm, int wn) {
  const int r = lane >> 2, t = lane & 3;
#pragma unroll
  for (int mi = 0; mi < 2; mi++)
#pragma unroll
    for (int nt = 0; nt < 8; nt++) {
      int m = wm * 32 + mi * 16 + r;
      int koff = (nt * 8 + 2 * t) * 2;
      uint32_t hi, lo;
      split2(P[mi][nt][0], P[mi][nt][1], hi, lo);
      *(uint32_t*)(smem + SM_AH + wn * A_CHUNK + m * PITCH + koff) = hi;
      *(uint32_t*)(smem + SM_AL + wn * A_CHUNK + m * PITCH + koff) = lo;
      split2(P[mi][nt][2], P[mi][nt][3], hi, lo);
      *(uint32_t*)(smem + SM_AH + wn * A_CHUNK + (m + 8) * PITCH + koff) = hi;
      *(uint32_t*)(smem + SM_AL + wn * A_CHUNK + (m + 8) * PITCH + koff) = lo;
    }
}

// ---------------------------------------------------------------------------
// Kernel: time attention + space ctx fused. grid (4 h-blocks, 256 bc).
//   out = main + Pacc_t @ V + V @ P_s
// ---------------------------------------------------------------------------
__global__ __launch_bounds__(256, 1) void time_space_fused_kernel(
    const float* __restrict__ mainx, float* __restrict__ out)
{
  extern __shared__ char smem[];
  uint32_t sb = smem_u32(smem);
  const int tid = threadIdx.x, lane = tid & 31, wid = tid >> 5;
  const int wm = wid & 1, wn = wid >> 1;
  const int bc = blockIdx.y, h0 = blockIdx.x * 64;
  const size_t pb = (size_t)bc * HWX;

  float Pacc[2][8][4], Sacc[2][8][4];
  zero_acc(Pacc);

  // ---- time scores: A <- Q straight; B <- K stream ----
  cpa_A(sb, g_qh, g_ql, pb + (size_t)h0 * WD, tid);
  cpa_B(sb, SM_B0H, SM_B0L, g_kh, g_kl, pb, 0, tid);
  CP_COMMIT();

  for (int c = 0; c < 16; c++) {
    int kc = c & 3;
    CP_WAIT0();
    __syncthreads();
    if (c + 1 < 16) {
      size_t b1 = ((size_t)((c + 1) >> 2) * 256 + bc) * HWX;
      uint32_t dh = ((c + 1) & 1) ? SM_B1H : SM_B0H;
      uint32_t dl = ((c + 1) & 1) ? SM_B1L : SM_B0L;
      cpa_B(sb, dh, dl, g_kh, g_kl, b1, ((c + 1) & 3) * 64, tid);
      CP_COMMIT();
    }
    if (kc == 0) zero_acc(Sacc);
    gemm_chunk(sb, kc, (c & 1) ? SM_B1H : SM_B0H, (c & 1) ? SM_B1L : SM_B0L, lane, wm, wn, Sacc);
    if (kc == 3) softmax_acc(smem, Sacc, Pacc, lane, wm, wn);
  }

  // ---- time ctx: A <- split(Pacc); B <- V^T stream; O_t in Sacc ----
  store_P_to_A(smem, Pacc, lane, wm, wn);
  zero_acc(Sacc);
  __syncthreads();
  cpa_B(sb, SM_B0H, SM_B0L, g_vth, g_vtl, pb, 0, tid);
  CP_COMMIT();
  for (int kc = 0; kc < 4; kc++) {
    CP_WAIT0();
    __syncthreads();
    if (kc + 1 < 4) {
      uint32_t dh = ((kc + 1) & 1) ? SM_B1H : SM_B0H;
      uint32_t dl = ((kc + 1) & 1) ? SM_B1L : SM_B0L;
      cpa_B(sb, dh, dl, g_vth, g_vtl, pb, (kc + 1) * 64, tid);
      CP_COMMIT();
    }
    gemm_chunk(sb, kc, (kc & 1) ? SM_B1H : SM_B0H, (kc & 1) ? SM_B1L : SM_B0L, lane, wm, wn, Sacc);
  }
  __syncthreads();   // all warps done reading A (P frags) before the V rewrite

  // ---- space ctx: A <- V straight; B <- psT stream; O_s in Pacc ----
  zero_acc(Pacc);
  cpa_A(sb, g_vh, g_vl, pb + (size_t)h0 * WD, tid);
  cpa_B(sb, SM_B0H, SM_B0L, g_psh, g_psl, pb, 0, tid);
  CP_COMMIT();
  for (int kc = 0; kc < 4; kc++) {
    CP_WAIT0();
    __syncthreads();
    if (kc + 1 < 4) {
      uint32_t dh = ((kc + 1) & 1) ? SM_B1H : SM_B0H;
      uint32_t dl = ((kc + 1) & 1) ? SM_B1L : SM_B0L;
      cpa_B(sb, dh, dl, g_psh, g_psl, pb, (kc + 1) * 64, tid);
      CP_COMMIT();
    }
    gemm_chunk(sb, kc, (kc & 1) ? SM_B1H : SM_B0H, (kc & 1) ? SM_B1L : SM_B0L, lane, wm, wn, Pacc);
  }

  // ---- single epilogue: out = main + O_t + O_s ----
  const float* mp = mainx + pb;
  float* op = out + pb;
  const int r = lane >> 2, t = lane & 3;
#pragma unroll
  for (int mi = 0; mi < 2; mi++)
#pragma unroll
    for (int nt = 0; nt < 8; nt++) {
      int row = h0 + wm * 32 + mi * 16 + r;
      int col = wn * 64 + nt * 8 + 2 * t;
      float2 m0 = *(const float2*)&mp[(size_t)row * WD + col];
      float2 m1 = *(const float2*)&mp[(size_t)(row + 8) * WD + col];
      *(float2*)&op[(size_t)row * WD + col] =
          make_float2(m0.x + Sacc[mi][nt][0] + Pacc[mi][nt][0],
                      m0.y + Sacc[mi][nt][1] + Pacc[mi][nt][1]);
      *(float2*)&op[(size_t)(row + 8) * WD + col] =
          make_float2(m1.x + Sacc[mi][nt][2] + Pacc[mi][nt][2],
                      m1.y + Sacc[mi][nt][3] + Pacc[mi][nt][3]);
    }
}

// ---------------------------------------------------------------------------
// Kernel: space scores -> psT (transposed, split). grid (4 w-blocks, 256 bc).
// Epilogue stages psT in smem (B0 region, free after mainloop) and writes
// coalesced 16B rows instead of scattered 2B stores.
// ---------------------------------------------------------------------------
__global__ __launch_bounds__(256, 1) void space_score_kernel()
{
  extern __shared__ char smem[];
  uint32_t sb = smem_u32(smem);
  const int tid = threadIdx.x, lane = tid & 31, wid = tid >> 5;
  const int wm = wid & 1, wn = wid >> 1;
  const int bc = blockIdx.y, w0 = blockIdx.x * 64;
  const size_t pb = (size_t)bc * HWX;

  float Pacc[2][8][4], Sacc[2][8][4];
  zero_acc(Pacc);

  cpa_A(sb, g_qth, g_qtl, pb + (size_t)w0 * WD, tid);
  cpa_B(sb, SM_B0H, SM_B0L, g_kth, g_ktl, pb, 0, tid);
  CP_COMMIT();

  for (int c = 0; c < 16; c++) {
    int kc = c & 3;
    CP_WAIT0();
    __syncthreads();
    if (c + 1 < 16) {
      size_t b1 = ((size_t)((c + 1) >> 2) * 256 + bc) * HWX;
      uint32_t dh = ((c + 1) & 1) ? SM_B1H : SM_B0H;
      uint32_t dl = ((c + 1) & 1) ? SM_B1L : SM_B0L;
      cpa_B(sb, dh, dl, g_kth, g_ktl, b1, ((c + 1) & 3) * 64, tid);
      CP_COMMIT();
    }
    if (kc == 0) zero_acc(Sacc);
    gemm_chunk(sb, kc, (c & 1) ? SM_B1H : SM_B0H, (c & 1) ? SM_B1L : SM_B0L, lane, wm, wn, Sacc);
    if (kc == 3) softmax_acc(smem, Sacc, Pacc, lane, wm, wn);
  }

  // stage fragments into smem psT tile [256 v][64 w] (hi in B0H, lo in B0L)
  __syncthreads();
  {
    char* ph = smem + SM_B0H;
    char* pl = smem + SM_B0L;
    const int r = lane >> 2, t = lane & 3;
#pragma unroll
    for (int mi = 0; mi < 2; mi++)
#pragma unroll
      for (int nt = 0; nt < 8; nt++) {
        int wl = wm * 32 + mi * 16 + r;
        int v  = wn * 64 + nt * 8 + 2 * t;
        __nv_bfloat16 h, l;
        split1(Pacc[mi][nt][0], h, l);
        *(__nv_bfloat16*)(ph + v * PITCH + wl * 2) = h;
        *(__nv_bfloat16*)(pl + v * PITCH + wl * 2) = l;
        split1(Pacc[mi][nt][1], h, l);
        *(__nv_bfloat16*)(ph + (v + 1) * PITCH + wl * 2) = h;
        *(__nv_bfloat16*)(pl + (v + 1) * PITCH + wl * 2) = l;
        split1(Pacc[mi][nt][2], h, l);
        *(__nv_bfloat16*)(ph + v * PITCH + (wl + 8) * 2) = h;
        *(__nv_bfloat16*)(pl + v * PITCH + (wl + 8) * 2) = l;
        split1(Pacc[mi][nt][3], h, l);
        *(__nv_bfloat16*)(ph + (v + 1) * PITCH + (wl + 8) * 2) = h;
        *(__nv_bfloat16*)(pl + (v + 1) * PITCH + (wl + 8) * 2) = l;
      }
  }
  __syncthreads();
  // coalesced copy: 256 v rows x 64 w (128B = 8 x 16B) per plane
  for (int idx = tid; idx < 4096; idx += 256) {
    int plane = idx >> 11, rem = idx & 2047;
    int v = rem >> 3, s = rem & 7;
    uint4 val = *(uint4*)(smem + (plane ? SM_B0L : SM_B0H) + v * PITCH + s * 16);
    *(uint4*)((plane ? g_psl : g_psh) + pb + (size_t)v * WD + w0 + s * 8) = val;
  }
}

// ---------------------------------------------------------------------------
// conv1x1 (FFMA) -> bf16 hi/lo outputs (x1 or x2)
// ---------------------------------------------------------------------------
template <bool DUAL>
__global__ __launch_bounds__(256, 1) void conv1x1_kernel(
    const float* __restrict__ x,
    const float* __restrict__ w1, const float* __restrict__ b1,
    __nv_bfloat16* __restrict__ y1h, __nv_bfloat16* __restrict__ y1l,
    const float* __restrict__ w2, const float* __restrict__ b2,
    __nv_bfloat16* __restrict__ y2h, __nv_bfloat16* __restrict__ y2l)
{
  extern __shared__ float sm[];
  float* Xs  = sm;
  float* W1s = sm + 4096;
  float* W2s = sm + 8192;

  const int tid = threadIdx.x;
  const int pb  = blockIdx.y;
  const int px0 = blockIdx.x * 64;
  const float* xp = x + (size_t)pb * CH * HWX;

#pragma unroll 4
  for (int idx = tid; idx < 4096; idx += 256) {
    W1s[idx] = w1[idx];
    if (DUAL) W2s[idx] = w2[idx];
    Xs[idx] = xp[(size_t)(idx >> 6) * HWX + px0 + (idx & 63)];
  }
  __syncthreads();

  const int ocg = tid >> 4;
  const int pxg = tid & 15;
  float a1[4][4] = {};
  float a2[4][4] = {};

#pragma unroll 8
  for (int i = 0; i < 64; i++) {
    float4 xv = *(const float4*)&Xs[i * 64 + pxg * 4];
#pragma unroll
    for (int r = 0; r < 4; r++) {
      float wv = W1s[(ocg * 4 + r) * 64 + i];
      a1[r][0] += wv * xv.x; a1[r][1] += wv * xv.y;
      a1[r][2] += wv * xv.z; a1[r][3] += wv * xv.w;
      if (DUAL) {
        float w2v = W2s[(ocg * 4 + r) * 64 + i];
        a2[r][0] += w2v * xv.x; a2[r][1] += w2v * xv.y;
        a2[r][2] += w2v * xv.z; a2[r][3] += w2v * xv.w;
      }
    }
  }

#pragma unroll
  for (int r = 0; r < 4; r++) {
    int oc = ocg * 4 + r;
    size_t base = (size_t)pb * CH * HWX + (size_t)oc * HWX + px0 + pxg * 4;
    float bb = b1[oc];
    uint32_t h0, l0, h1, l1;
    split2(a1[r][0] + bb, a1[r][1] + bb, h0, l0);
    split2(a1[r][2] + bb, a1[r][3] + bb, h1, l1);
    *(uint2*)(y1h + base) = make_uint2(h0, h1);
    *(uint2*)(y1l + base) = make_uint2(l0, l1);
    if (DUAL) {
      float bb2 = b2[oc];
      split2(a2[r][0] + bb2, a2[r][1] + bb2, h0, l0);
      split2(a2[r][2] + bb2, a2[r][3] + bb2, h1, l1);
      *(uint2*)(y2h + base) = make_uint2(h0, h1);
      *(uint2*)(y2l + base) = make_uint2(l0, l1);
    }
  }
}

// ---------------------------------------------------------------------------
// packed transpose: dst[p][w*256+h] = src[p][h*256+w], hi+lo planes.
// 64(h) x 256(w) tiles, dynamic smem [2][256][33] u32, 4 blocks/plane.
// ---------------------------------------------------------------------------
__global__ __launch_bounds__(256, 1) void transpose_kernel(
    const __nv_bfloat16* __restrict__ srcH, const __nv_bfloat16* __restrict__ srcL,
    __nv_bfloat16* __restrict__ dstH, __nv_bfloat16* __restrict__ dstL)
{
  extern __shared__ uint32_t tl[];   // [2][256][33]
  const int p = blockIdx.x, h0 = blockIdx.y * 64;
  const size_t base = (size_t)p * HWX;
  const int tid = threadIdx.x;

  // load + pack: plane(2) x hp(32) x w4(64)
  for (int idx = tid; idx < 4096; idx += 256) {
    int plane = idx >> 11, rem = idx & 2047;
    int hp = rem >> 6, w4 = rem & 63;
    const __nv_bfloat16* s = (plane ? srcL : srcH) + base + (size_t)(h0 + 2 * hp) * WD + w4 * 4;
    uint2 a = *(const uint2*)s;
    uint2 b = *(const uint2*)(s + WD);
    uint32_t* t = tl + plane * 8448 + (w4 * 4) * 33 + hp;
    t[0]  = __byte_perm(a.x, b.x, 0x5410);
    t[33] = __byte_perm(a.x, b.x, 0x7632);
    t[66] = __byte_perm(a.y, b.y, 0x5410);
    t[99] = __byte_perm(a.y, b.y, 0x7632);
  }
  __syncthreads();

  // store: plane(2) x w(256) x oct(8 x 16B)
  for (int idx = tid; idx < 4096; idx += 256) {
    int plane = idx >> 11, rem = idx & 2047;
    int w = rem >> 3, oct = rem & 7;
    const uint32_t* t = tl + plane * 8448 + w * 33 + oct * 4;
    uint4 v;
    v.x = t[0]; v.y = t[1]; v.z = t[2]; v.w = t[3];
    __nv_bfloat16* d = (plane ? dstL : dstH) + base + (size_t)w * WD + h0 + oct * 8;
    *(uint4*)d = v;
  }
}

// ---------------------------------------------------------------------------
extern "C" void kernel_launch(void* const* d_in, const int* in_sizes, int n_in,
                              void* d_out, int out_size)
{
  (void)in_sizes; (void)n_in; (void)out_size;
  const float* mainx  = (const float*)d_in[0];
  const float* assist = (const float*)d_in[1];
  const float* wq = (const float*)d_in[2];
  const float* bq = (const float*)d_in[3];
  const float* wk = (const float*)d_in[4];
  const float* bk = (const float*)d_in[5];
  const float* wv = (const float*)d_in[6];
  const float* bv = (const float*)d_in[7];
  float* out = (float*)d_out;

  __nv_bfloat16 *qh, *ql, *vh, *vl, *kh, *kl, *qth, *qtl, *vth, *vtl, *kth, *ktl;
  cudaGetSymbolAddress((void**)&qh,  g_qh);  cudaGetSymbolAddress((void**)&ql,  g_ql);
  cudaGetSymbolAddress((void**)&vh,  g_vh);  cudaGetSymbolAddress((void**)&vl,  g_vl);
  cudaGetSymbolAddress((void**)&kh,  g_kh);  cudaGetSymbolAddress((void**)&kl,  g_kl);
  cudaGetSymbolAddress((void**)&qth, g_qth); cudaGetSymbolAddress((void**)&qtl, g_qtl);
  cudaGetSymbolAddress((void**)&vth, g_vth); cudaGetSymbolAddress((void**)&vtl, g_vtl);
  cudaGetSymbolAddress((void**)&kth, g_kth); cudaGetSymbolAddress((void**)&ktl, g_ktl);

  cudaFuncSetAttribute(conv1x1_kernel<true>,  cudaFuncAttributeMaxDynamicSharedMemorySize, 49152);
  cudaFuncSetAttribute(conv1x1_kernel<false>, cudaFuncAttributeMaxDynamicSharedMemorySize, 32768);
  cudaFuncSetAttribute(transpose_kernel, cudaFuncAttributeMaxDynamicSharedMemorySize, TP_SMEM);
  cudaFuncSetAttribute(time_space_fused_kernel, cudaFuncAttributeMaxDynamicSharedMemorySize, SM_TOTAL);
  cudaFuncSetAttribute(space_score_kernel,      cudaFuncAttributeMaxDynamicSharedMemorySize, SM_TOTAL);

  static cudaStream_t s2 = 0;
  static cudaEvent_t evFork = 0, evJoin = 0;
  static bool tried = false;
  if (!tried) {
    tried = true;
    if (cudaStreamCreateWithFlags(&s2, cudaStreamNonBlocking) != cudaSuccess) s2 = 0;
    if (s2) {
      if (cudaEventCreateWithFlags(&evFork, cudaEventDisableTiming) != cudaSuccess ||
          cudaEventCreateWithFlags(&evJoin, cudaEventDisableTiming) != cudaSuccess) {
        s2 = 0;
      }
    }
  }

  if (s2) {
    cudaEventRecord(evFork, 0);
    cudaStreamWaitEvent(s2, evFork, 0);
    conv1x1_kernel<false><<<dim3(1024, 16), 256, 32768, s2>>>(assist, wk, bk, kh, kl,
                                                              (const float*)0, (const float*)0,
                                                              (__nv_bfloat16*)0, (__nv_bfloat16*)0);
    transpose_kernel<<<dim3(1024, 4), 256, TP_SMEM, s2>>>(kh, kl, kth, ktl);
    cudaEventRecord(evJoin, s2);

    conv1x1_kernel<true><<<dim3(1024, 4), 256, 49152>>>(mainx, wq, bq, qh, ql, wv, bv, vh, vl);
    transpose_kernel<<<dim3(256, 4), 256, TP_SMEM>>>(qh, ql, qth, qtl);
    transpose_kernel<<<dim3(256, 4), 256, TP_SMEM>>>(vh, vl, vth, vtl);

    cudaStreamWaitEvent(0, evJoin, 0);
    space_score_kernel<<<dim3(4, 256), 256, SM_TOTAL>>>();
    time_space_fused_kernel<<<dim3(4, 256), 256, SM_TOTAL>>>(mainx, out);
  } else {
    conv1x1_kernel<true><<<dim3(1024, 4), 256, 49152>>>(mainx, wq, bq, qh, ql, wv, bv, vh, vl);
    conv1x1_kernel<false><<<dim3(1024, 16), 256, 32768>>>(assist, wk, bk, kh, kl,
                                                          (const float*)0, (const float*)0,
                                                          (__nv_bfloat16*)0, (__nv_bfloat16*)0);
    transpose_kernel<<<dim3(256, 4), 256, TP_SMEM>>>(qh, ql, qth, qtl);
    transpose_kernel<<<dim3(256, 4), 256, TP_SMEM>>>(vh, vl, vth, vtl);
    transpose_kernel<<<dim3(1024, 4), 256, TP_SMEM>>>(kh, kl, kth, ktl);
    space_score_kernel<<<dim3(4, 256), 256, SM_TOTAL>>>();
    time_space_fused_kernel<<<dim3(4, 256), 256, SM_TOTAL>>>(mainx, out);
  }
}

// round 16
// speedup vs baseline: 1.0491x; 1.0491x over previous
#include <cuda_runtime.h>
#include <cuda_bf16.h>
#include <cstdint>

static const int HWX = 65536;   // 256*256
static const int WD  = 256;
static const int CH  = 64;

// ---------------------------------------------------------------------------
// Scratch: everything pre-split into bf16 hi/lo, straight and transposed.
// ---------------------------------------------------------------------------
__device__ __nv_bfloat16 g_qh[16777216],  g_ql[16777216];
__device__ __nv_bfloat16 g_vh[16777216],  g_vl[16777216];
__device__ __nv_bfloat16 g_kh[67108864],  g_kl[67108864];
__device__ __nv_bfloat16 g_qth[16777216], g_qtl[16777216];
__device__ __nv_bfloat16 g_vth[16777216], g_vtl[16777216];
__device__ __nv_bfloat16 g_kth[67108864], g_ktl[67108864];
__device__ __nv_bfloat16 g_psh[16777216], g_psl[16777216];  // sum_n P_space, TRANSPOSED [v][w]

// ---------------------------------------------------------------------------
// SMEM layout (attention). PITCH 144 B per 64-k row -> conflict-free ldmatrix.
// ---------------------------------------------------------------------------
static const int PITCH   = 144;
static const int A_CHUNK = 64 * PITCH;              // 9216
static const int SM_AH   = 0;                       // 4*9216 = 36864
static const int SM_AL   = 36864;
static const int B_PLANE = 256 * PITCH;             // 36864
static const int SM_B0H  = 73728;
static const int SM_B0L  = SM_B0H + B_PLANE;        // 110592
static const int SM_B1H  = SM_B0L + B_PLANE;        // 147456
static const int SM_B1L  = SM_B1H + B_PLANE;        // 184320
static const int SM_RS   = SM_B1L + B_PLANE;        // 221184 ([4][64] floats)
static const int SM_TOTAL = SM_RS + 1024;           // 222208

// ---------------------------------------------------------------------------
// Helpers
// ---------------------------------------------------------------------------
__device__ __forceinline__ uint32_t smem_u32(const void* p) {
  uint32_t a;
  asm("{ .reg .u64 t; cvta.to.shared.u64 t, %1; cvt.u32.u64 %0, t; }" : "=r"(a) : "l"(p));
  return a;
}
__device__ __forceinline__ void split2(float x0, float x1, uint32_t& hi2, uint32_t& lo2) {
  __nv_bfloat162 h = __floats2bfloat162_rn(x0, x1);
  float r0 = x0 - __bfloat162float(h.x);
  float r1 = x1 - __bfloat162float(h.y);
  __nv_bfloat162 l = __floats2bfloat162_rn(r0, r1);
  hi2 = *(uint32_t*)&h;
  lo2 = *(uint32_t*)&l;
}
__device__ __forceinline__ void split1(float x, __nv_bfloat16& h, __nv_bfloat16& l) {
  h = __float2bfloat16(x);
  l = __float2bfloat16(x - __bfloat162float(h));
}

__device__ __forceinline__ void mma16816(float c[4], uint32_t a0, uint32_t a1,
                                         uint32_t a2, uint32_t a3,
                                         uint32_t b0, uint32_t b1) {
  asm volatile(
    "mma.sync.aligned.m16n8k16.row.col.f32.bf16.bf16.f32 "
    "{%0,%1,%2,%3}, {%4,%5,%6,%7}, {%8,%9}, {%0,%1,%2,%3};"
    : "+f"(c[0]), "+f"(c[1]), "+f"(c[2]), "+f"(c[3])
    : "r"(a0), "r"(a1), "r"(a2), "r"(a3), "r"(b0), "r"(b1));
}
__device__ __forceinline__ void ldmx4(uint32_t& r0, uint32_t& r1, uint32_t& r2, uint32_t& r3,
                                      uint32_t addr) {
  asm volatile("ldmatrix.sync.aligned.m8n8.x4.shared.b16 {%0,%1,%2,%3}, [%4];"
               : "=r"(r0), "=r"(r1), "=r"(r2), "=r"(r3) : "r"(addr));
}

#define CP16(dst, src)  asm volatile("cp.async.cg.shared.global [%0], [%1], 16;" :: "r"(dst), "l"(src))
#define CP_COMMIT()     asm volatile("cp.async.commit_group;" ::: "memory")
#define CP_WAIT0()      asm volatile("cp.async.wait_group 0;" ::: "memory")

// A fill (all 4 k-chunks, 64 rows): strength-reduced pointer-marching copies.
__device__ __forceinline__ void cpa_A(uint32_t sb, const __nv_bfloat16* srcH,
                                      const __nv_bfloat16* srcL, size_t rowbase, int tid) {
  const int m0 = tid >> 5, s = tid & 31;
  const __nv_bfloat16* pH = srcH + rowbase + (size_t)m0 * WD + s * 8;
  const __nv_bfloat16* pL = srcL + rowbase + (size_t)m0 * WD + s * 8;
  const uint32_t off = (uint32_t)((s >> 3) * A_CHUNK + m0 * PITCH + (s & 7) * 16);
  uint32_t dh = sb + SM_AH + off, dl = sb + SM_AL + off;
#pragma unroll
  for (int j = 0; j < 8; j++) {
    CP16(dh, pH);
    CP16(dl, pL);
    pH += 8 * WD; pL += 8 * WD;
    dh += 8 * PITCH; dl += 8 * PITCH;
  }
}
// B fill (one 64-k chunk, 256 rows)
__device__ __forceinline__ void cpa_B(uint32_t sb, uint32_t dH, uint32_t dL,
                                      const __nv_bfloat16* srcH, const __nv_bfloat16* srcL,
                                      size_t base, int koff, int tid) {
  const int n0 = tid >> 3, s = tid & 7;
  const __nv_bfloat16* pH = srcH + base + (size_t)n0 * WD + koff + s * 8;
  const __nv_bfloat16* pL = srcL + base + (size_t)n0 * WD + koff + s * 8;
  uint32_t dh = sb + dH + (uint32_t)(n0 * PITCH + s * 16);
  uint32_t dl = sb + dL + (uint32_t)(n0 * PITCH + s * 16);
#pragma unroll
  for (int j = 0; j < 8; j++) {
    CP16(dh, pH);
    CP16(dl, pL);
    pH += 32 * WD; pL += 32 * WD;
    dh += 32 * PITCH; dl += 32 * PITCH;
  }
}

// ---------------------------------------------------------------------------
// One 64-k chunk: acc[2][8][4] += A_chunk * B^T  (3-term bf16 split)
// Warp tile 32(M) x 64(N): wm in {0,1}, wn in {0..3}. 8 warps.
// ---------------------------------------------------------------------------
__device__ __forceinline__ void gemm_chunk(uint32_t sb, int ac, uint32_t bufH, uint32_t bufL,
                                           int lane, int wm, int wn, float (&acc)[2][8][4]) {
  const int i8 = lane & 7, q = lane >> 3;
  uint32_t bAddr = sb + (q < 2 ? bufH : bufL) + (uint32_t)(wn * 64 + i8) * PITCH + (q & 1) * 16;
  const int i16 = lane & 15, hsel = lane >> 4;
  uint32_t aAddrH = sb + SM_AH + ac * A_CHUNK + (uint32_t)(wm * 32 + i16) * PITCH + hsel * 16;
  uint32_t aAddrL = aAddrH + (SM_AL - SM_AH);
#pragma unroll
  for (int kt = 0; kt < 4; kt++) {
    uint32_t h00, h01, h02, h03, h10, h11, h12, h13;
    uint32_t l00, l01, l02, l03, l10, l11, l12, l13;
    ldmx4(h00, h01, h02, h03, aAddrH + kt * 32);
    ldmx4(h10, h11, h12, h13, aAddrH + 16 * PITCH + kt * 32);
    ldmx4(l00, l01, l02, l03, aAddrL + kt * 32);
    ldmx4(l10, l11, l12, l13, aAddrL + 16 * PITCH + kt * 32);
#pragma unroll
    for (int nt = 0; nt < 8; nt++) {
      uint32_t b0, b1, b2, b3;  // bh0, bh1, bl0, bl1 in ONE ldmatrix
      ldmx4(b0, b1, b2, b3, bAddr + nt * 8 * PITCH + kt * 32);
      mma16816(acc[0][nt], h00, h01, h02, h03, b0, b1);
      mma16816(acc[1][nt], h10, h11, h12, h13, b0, b1);
      mma16816(acc[0][nt], l00, l01, l02, l03, b0, b1);
      mma16816(acc[1][nt], l10, l11, l12, l13, b0, b1);
      mma16816(acc[0][nt], h00, h01, h02, h03, b2, b3);
      mma16816(acc[1][nt], h10, h11, h12, h13, b2, b3);
    }
  }
}

__device__ __forceinline__ void zero_acc(float (&a)[2][8][4]) {
#pragma unroll
  for (int mi = 0; mi < 2; mi++)
#pragma unroll
    for (int nt = 0; nt < 8; nt++)
#pragma unroll
      for (int e = 0; e < 4; e++) a[mi][nt][e] = 0.f;
}

// softmax over full 256-wide rows (cols span the 4 wn warps), accumulate into P
__device__ __forceinline__ void softmax_acc(char* smem, float (&S)[2][8][4], float (&P)[2][8][4],
                                            int lane, int wm, int wn) {
  const int r = lane >> 2, t = lane & 3;
  float* rs = (float*)(smem + SM_RS);  // [4 wn][64 rows]
  float s[4] = {0.f, 0.f, 0.f, 0.f};
#pragma unroll
  for (int mi = 0; mi < 2; mi++)
#pragma unroll
    for (int nt = 0; nt < 8; nt++) {
#pragma unroll
      for (int e = 0; e < 4; e++) S[mi][nt][e] = __expf(S[mi][nt][e] * 0.0625f);
      s[mi * 2 + 0] += S[mi][nt][0] + S[mi][nt][1];
      s[mi * 2 + 1] += S[mi][nt][2] + S[mi][nt][3];
    }
#pragma unroll
  for (int o = 1; o <= 2; o <<= 1)
#pragma unroll
    for (int i = 0; i < 4; i++) s[i] += __shfl_xor_sync(0xffffffffu, s[i], o);
  if (t == 0) {
#pragma unroll
    for (int mi = 0; mi < 2; mi++) {
      rs[wn * 64 + wm * 32 + mi * 16 + r]     = s[mi * 2 + 0];
      rs[wn * 64 + wm * 32 + mi * 16 + r + 8] = s[mi * 2 + 1];
    }
  }
  __syncthreads();
#pragma unroll
  for (int mi = 0; mi < 2; mi++) {
    int row = wm * 32 + mi * 16 + r;
    float inv0 = 1.0f / (rs[row] + rs[64 + row] + rs[128 + row] + rs[192 + row]);
    float inv1 = 1.0f / (rs[row + 8] + rs[64 + row + 8] + rs[128 + row + 8] + rs[192 + row + 8]);
#pragma unroll
    for (int nt = 0; nt < 8; nt++) {
      P[mi][nt][0] += S[mi][nt][0] * inv0;
      P[mi][nt][1] += S[mi][nt][1] * inv0;
      P[mi][nt][2] += S[mi][nt][2] * inv1;
      P[mi][nt][3] += S[mi][nt][3] * inv1;
    }
  }
  __syncthreads();
}

// write P fragments into the A smem region (split, fragment-native layout)
__device__ __forceinline__ void store_P_to_A(char* smem, const float (&P)[2][8][4],
                                             int lane, int wm, int wn) {
  const int r = lane >> 2, t = lane & 3;
#pragma unroll
  for (int mi = 0; mi < 2; mi++)
#pragma unroll
    for (int nt = 0; nt < 8; nt++) {
      int m = wm * 32 + mi * 16 + r;
      int koff = (nt * 8 + 2 * t) * 2;
      uint32_t hi, lo;
      split2(P[mi][nt][0], P[mi][nt][1], hi, lo);
      *(uint32_t*)(smem + SM_AH + wn * A_CHUNK + m * PITCH + koff) = hi;
      *(uint32_t*)(smem + SM_AL + wn * A_CHUNK + m * PITCH + koff) = lo;
      split2(P[mi][nt][2], P[mi][nt][3], hi, lo);
      *(uint32_t*)(smem + SM_AH + wn * A_CHUNK + (m + 8) * PITCH + koff) = hi;
      *(uint32_t*)(smem + SM_AL + wn * A_CHUNK + (m + 8) * PITCH + koff) = lo;
    }
}

// ---------------------------------------------------------------------------
// Kernel: time attention + space ctx fused. grid (4 h-blocks, 256 bc).
//   out = main + Pacc_t @ V + V @ P_s
// ---------------------------------------------------------------------------
__global__ __launch_bounds__(256, 1) void time_space_fused_kernel(
    const float* __restrict__ mainx, float* __restrict__ out)
{
  extern __shared__ char smem[];
  uint32_t sb = smem_u32(smem);
  const int tid = threadIdx.x, lane = tid & 31, wid = tid >> 5;
  const int wm = wid & 1, wn = wid >> 1;
  const int bc = blockIdx.y, h0 = blockIdx.x * 64;
  const size_t pb = (size_t)bc * HWX;

  float Pacc[2][8][4], Sacc[2][8][4];
  zero_acc(Pacc);

  // ---- time scores: A <- Q straight; B <- K stream ----
  cpa_A(sb, g_qh, g_ql, pb + (size_t)h0 * WD, tid);
  cpa_B(sb, SM_B0H, SM_B0L, g_kh, g_kl, pb, 0, tid);
  CP_COMMIT();

  for (int c = 0; c < 16; c++) {
    int kc = c & 3;
    CP_WAIT0();
    __syncthreads();
    if (c + 1 < 16) {
      size_t b1 = ((size_t)((c + 1) >> 2) * 256 + bc) * HWX;
      uint32_t dh = ((c + 1) & 1) ? SM_B1H : SM_B0H;
      uint32_t dl = ((c + 1) & 1) ? SM_B1L : SM_B0L;
      cpa_B(sb, dh, dl, g_kh, g_kl, b1, ((c + 1) & 3) * 64, tid);
      CP_COMMIT();
    }
    if (kc == 0) zero_acc(Sacc);
    gemm_chunk(sb, kc, (c & 1) ? SM_B1H : SM_B0H, (c & 1) ? SM_B1L : SM_B0L, lane, wm, wn, Sacc);
    if (kc == 3) softmax_acc(smem, Sacc, Pacc, lane, wm, wn);
  }

  // ---- time ctx: A <- split(Pacc); B <- V^T stream; O_t in Sacc ----
  store_P_to_A(smem, Pacc, lane, wm, wn);
  zero_acc(Sacc);
  __syncthreads();
  cpa_B(sb, SM_B0H, SM_B0L, g_vth, g_vtl, pb, 0, tid);
  CP_COMMIT();
  for (int kc = 0; kc < 4; kc++) {
    CP_WAIT0();
    __syncthreads();
    if (kc + 1 < 4) {
      uint32_t dh = ((kc + 1) & 1) ? SM_B1H : SM_B0H;
      uint32_t dl = ((kc + 1) & 1) ? SM_B1L : SM_B0L;
      cpa_B(sb, dh, dl, g_vth, g_vtl, pb, (kc + 1) * 64, tid);
      CP_COMMIT();
    }
    gemm_chunk(sb, kc, (kc & 1) ? SM_B1H : SM_B0H, (kc & 1) ? SM_B1L : SM_B0L, lane, wm, wn, Sacc);
  }
  __syncthreads();   // all warps done reading A (P frags) before the V rewrite

  // ---- space ctx: A <- V straight; B <- psT stream; O_s in Pacc ----
  zero_acc(Pacc);
  cpa_A(sb, g_vh, g_vl, pb + (size_t)h0 * WD, tid);
  cpa_B(sb, SM_B0H, SM_B0L, g_psh, g_psl, pb, 0, tid);
  CP_COMMIT();
  for (int kc = 0; kc < 4; kc++) {
    CP_WAIT0();
    __syncthreads();
    if (kc + 1 < 4) {
      uint32_t dh = ((kc + 1) & 1) ? SM_B1H : SM_B0H;
      uint32_t dl = ((kc + 1) & 1) ? SM_B1L : SM_B0L;
      cpa_B(sb, dh, dl, g_psh, g_psl, pb, (kc + 1) * 64, tid);
      CP_COMMIT();
    }
    gemm_chunk(sb, kc, (kc & 1) ? SM_B1H : SM_B0H, (kc & 1) ? SM_B1L : SM_B0L, lane, wm, wn, Pacc);
  }

  // ---- single epilogue: out = main + O_t + O_s ----
  const float* mp = mainx + pb;
  float* op = out + pb;
  const int r = lane >> 2, t = lane & 3;
#pragma unroll
  for (int mi = 0; mi < 2; mi++)
#pragma unroll
    for (int nt = 0; nt < 8; nt++) {
      int row = h0 + wm * 32 + mi * 16 + r;
      int col = wn * 64 + nt * 8 + 2 * t;
      float2 m0 = *(const float2*)&mp[(size_t)row * WD + col];
      float2 m1 = *(const float2*)&mp[(size_t)(row + 8) * WD + col];
      *(float2*)&op[(size_t)row * WD + col] =
          make_float2(m0.x + Sacc[mi][nt][0] + Pacc[mi][nt][0],
                      m0.y + Sacc[mi][nt][1] + Pacc[mi][nt][1]);
      *(float2*)&op[(size_t)(row + 8) * WD + col] =
          make_float2(m1.x + Sacc[mi][nt][2] + Pacc[mi][nt][2],
                      m1.y + Sacc[mi][nt][3] + Pacc[mi][nt][3]);
    }
}

// ---------------------------------------------------------------------------
// Kernel: space scores -> psT (transposed, split). grid (4 w-blocks, 256 bc).
// Epilogue stages psT in smem (B0 region, free after mainloop) and writes
// coalesced 16B rows instead of scattered 2B stores.
// ---------------------------------------------------------------------------
__global__ __launch_bounds__(256, 1) void space_score_kernel()
{
  extern __shared__ char smem[];
  uint32_t sb = smem_u32(smem);
  const int tid = threadIdx.x, lane = tid & 31, wid = tid >> 5;
  const int wm = wid & 1, wn = wid >> 1;
  const int bc = blockIdx.y, w0 = blockIdx.x * 64;
  const size_t pb = (size_t)bc * HWX;

  float Pacc[2][8][4], Sacc[2][8][4];
  zero_acc(Pacc);

  cpa_A(sb, g_qth, g_qtl, pb + (size_t)w0 * WD, tid);
  cpa_B(sb, SM_B0H, SM_B0L, g_kth, g_ktl, pb, 0, tid);
  CP_COMMIT();

  for (int c = 0; c < 16; c++) {
    int kc = c & 3;
    CP_WAIT0();
    __syncthreads();
    if (c + 1 < 16) {
      size_t b1 = ((size_t)((c + 1) >> 2) * 256 + bc) * HWX;
      uint32_t dh = ((c + 1) & 1) ? SM_B1H : SM_B0H;
      uint32_t dl = ((c + 1) & 1) ? SM_B1L : SM_B0L;
      cpa_B(sb, dh, dl, g_kth, g_ktl, b1, ((c + 1) & 3) * 64, tid);
      CP_COMMIT();
    }
    if (kc == 0) zero_acc(Sacc);
    gemm_chunk(sb, kc, (c & 1) ? SM_B1H : SM_B0H, (c & 1) ? SM_B1L : SM_B0L, lane, wm, wn, Sacc);
    if (kc == 3) softmax_acc(smem, Sacc, Pacc, lane, wm, wn);
  }

  // stage fragments into smem psT tile [256 v][64 w] (hi in B0H, lo in B0L)
  __syncthreads();
  {
    char* ph = smem + SM_B0H;
    char* pl = smem + SM_B0L;
    const int r = lane >> 2, t = lane & 3;
#pragma unroll
    for (int mi = 0; mi < 2; mi++)
#pragma unroll
      for (int nt = 0; nt < 8; nt++) {
        int wl = wm * 32 + mi * 16 + r;
        int v  = wn * 64 + nt * 8 + 2 * t;
        __nv_bfloat16 h, l;
        split1(Pacc[mi][nt][0], h, l);
        *(__nv_bfloat16*)(ph + v * PITCH + wl * 2) = h;
        *(__nv_bfloat16*)(pl + v * PITCH + wl * 2) = l;
        split1(Pacc[mi][nt][1], h, l);
        *(__nv_bfloat16*)(ph + (v + 1) * PITCH + wl * 2) = h;
        *(__nv_bfloat16*)(pl + (v + 1) * PITCH + wl * 2) = l;
        split1(Pacc[mi][nt][2], h, l);
        *(__nv_bfloat16*)(ph + v * PITCH + (wl + 8) * 2) = h;
        *(__nv_bfloat16*)(pl + v * PITCH + (wl + 8) * 2) = l;
        split1(Pacc[mi][nt][3], h, l);
        *(__nv_bfloat16*)(ph + (v + 1) * PITCH + (wl + 8) * 2) = h;
        *(__nv_bfloat16*)(pl + (v + 1) * PITCH + (wl + 8) * 2) = l;
      }
  }
  __syncthreads();
  // coalesced copy: 256 v rows x 64 w (128B = 8 x 16B) per plane
  for (int idx = tid; idx < 4096; idx += 256) {
    int plane = idx >> 11, rem = idx & 2047;
    int v = rem >> 3, s = rem & 7;
    uint4 val = *(uint4*)(smem + (plane ? SM_B0L : SM_B0H) + v * PITCH + s * 16);
    *(uint4*)((plane ? g_psl : g_psh) + pb + (size_t)v * WD + w0 + s * 8) = val;
  }
}

// ---------------------------------------------------------------------------
// conv1x1 (FFMA) -> bf16 hi/lo outputs (x1 or x2)
// ---------------------------------------------------------------------------
template <bool DUAL>
__global__ __launch_bounds__(256, 1) void conv1x1_kernel(
    const float* __restrict__ x,
    const float* __restrict__ w1, const float* __restrict__ b1,
    __nv_bfloat16* __restrict__ y1h, __nv_bfloat16* __restrict__ y1l,
    const float* __restrict__ w2, const float* __restrict__ b2,
    __nv_bfloat16* __restrict__ y2h, __nv_bfloat16* __restrict__ y2l)
{
  extern __shared__ float sm[];
  float* Xs  = sm;
  float* W1s = sm + 4096;
  float* W2s = sm + 8192;

  const int tid = threadIdx.x;
  const int pb  = blockIdx.y;
  const int px0 = blockIdx.x * 64;
  const float* xp = x + (size_t)pb * CH * HWX;

#pragma unroll 4
  for (int idx = tid; idx < 4096; idx += 256) {
    W1s[idx] = w1[idx];
    if (DUAL) W2s[idx] = w2[idx];
    Xs[idx] = xp[(size_t)(idx >> 6) * HWX + px0 + (idx & 63)];
  }
  __syncthreads();

  const int ocg = tid >> 4;
  const int pxg = tid & 15;
  float a1[4][4] = {};
  float a2[4][4] = {};

#pragma unroll 8
  for (int i = 0; i < 64; i++) {
    float4 xv = *(const float4*)&Xs[i * 64 + pxg * 4];
#pragma unroll
    for (int r = 0; r < 4; r++) {
      float wv = W1s[(ocg * 4 + r) * 64 + i];
      a1[r][0] += wv * xv.x; a1[r][1] += wv * xv.y;
      a1[r][2] += wv * xv.z; a1[r][3] += wv * xv.w;
      if (DUAL) {
        float w2v = W2s[(ocg * 4 + r) * 64 + i];
        a2[r][0] += w2v * xv.x; a2[r][1] += w2v * xv.y;
        a2[r][2] += w2v * xv.z; a2[r][3] += w2v * xv.w;
      }
    }
  }

#pragma unroll
  for (int r = 0; r < 4; r++) {
    int oc = ocg * 4 + r;
    size_t base = (size_t)pb * CH * HWX + (size_t)oc * HWX + px0 + pxg * 4;
    float bb = b1[oc];
    uint32_t h0, l0, h1, l1;
    split2(a1[r][0] + bb, a1[r][1] + bb, h0, l0);
    split2(a1[r][2] + bb, a1[r][3] + bb, h1, l1);
    *(uint2*)(y1h + base) = make_uint2(h0, h1);
    *(uint2*)(y1l + base) = make_uint2(l0, l1);
    if (DUAL) {
      float bb2 = b2[oc];
      split2(a2[r][0] + bb2, a2[r][1] + bb2, h0, l0);
      split2(a2[r][2] + bb2, a2[r][3] + bb2, h1, l1);
      *(uint2*)(y2h + base) = make_uint2(h0, h1);
      *(uint2*)(y2l + base) = make_uint2(l0, l1);
    }
  }
}

// ---------------------------------------------------------------------------
// packed transpose (R13-validated): dst[p][w*256+h] = src[p][h*256+w].
// 64x64 tiles, static smem, grid (planes, 16), occ ~86%.
// ---------------------------------------------------------------------------
__global__ __launch_bounds__(256, 1) void transpose_kernel(
    const __nv_bfloat16* __restrict__ srcH, const __nv_bfloat16* __restrict__ srcL,
    __nv_bfloat16* __restrict__ dstH, __nv_bfloat16* __restrict__ dstL)
{
  __shared__ uint32_t tile[2][64][33];
  const int p = blockIdx.x, tIdx = blockIdx.y;
  const int h0 = (tIdx >> 2) * 64, w0 = (tIdx & 3) * 64;
  const size_t base = (size_t)p * HWX;
  const int tid = threadIdx.x;

  for (int idx = tid; idx < 1024; idx += 256) {
    int plane = idx >> 9, rem = idx & 511;
    int hp = rem >> 4, w4 = rem & 15;
    const __nv_bfloat16* s = (plane ? srcL : srcH) + base + (size_t)(h0 + 2 * hp) * WD + w0 + w4 * 4;
    uint2 a = *(const uint2*)s;
    uint2 b = *(const uint2*)(s + WD);
    tile[plane][w4 * 4 + 0][hp] = __byte_perm(a.x, b.x, 0x5410);
    tile[plane][w4 * 4 + 1][hp] = __byte_perm(a.x, b.x, 0x7632);
    tile[plane][w4 * 4 + 2][hp] = __byte_perm(a.y, b.y, 0x5410);
    tile[plane][w4 * 4 + 3][hp] = __byte_perm(a.y, b.y, 0x7632);
  }
  __syncthreads();

  for (int idx = tid; idx < 1024; idx += 256) {
    int plane = idx >> 9, rem = idx & 511;
    int w = rem >> 3, oct = rem & 7;
    uint4 v;
    v.x = tile[plane][w][oct * 4 + 0];
    v.y = tile[plane][w][oct * 4 + 1];
    v.z = tile[plane][w][oct * 4 + 2];
    v.w = tile[plane][w][oct * 4 + 3];
    __nv_bfloat16* d = (plane ? dstL : dstH) + base + (size_t)(w0 + w) * WD + h0 + oct * 8;
    *(uint4*)d = v;
  }
}

// ---------------------------------------------------------------------------
extern "C" void kernel_launch(void* const* d_in, const int* in_sizes, int n_in,
                              void* d_out, int out_size)
{
  (void)in_sizes; (void)n_in; (void)out_size;
  const float* mainx  = (const float*)d_in[0];
  const float* assist = (const float*)d_in[1];
  const float* wq = (const float*)d_in[2];
  const float* bq = (const float*)d_in[3];
  const float* wk = (const float*)d_in[4];
  const float* bk = (const float*)d_in[5];
  const float* wv = (const float*)d_in[6];
  const float* bv = (const float*)d_in[7];
  float* out = (float*)d_out;

  __nv_bfloat16 *qh, *ql, *vh, *vl, *kh, *kl, *qth, *qtl, *vth, *vtl, *kth, *ktl;
  cudaGetSymbolAddress((void**)&qh,  g_qh);  cudaGetSymbolAddress((void**)&ql,  g_ql);
  cudaGetSymbolAddress((void**)&vh,  g_vh);  cudaGetSymbolAddress((void**)&vl,  g_vl);
  cudaGetSymbolAddress((void**)&kh,  g_kh);  cudaGetSymbolAddress((void**)&kl,  g_kl);
  cudaGetSymbolAddress((void**)&qth, g_qth); cudaGetSymbolAddress((void**)&qtl, g_qtl);
  cudaGetSymbolAddress((void**)&vth, g_vth); cudaGetSymbolAddress((void**)&vtl, g_vtl);
  cudaGetSymbolAddress((void**)&kth, g_kth); cudaGetSymbolAddress((void**)&ktl, g_ktl);

  cudaFuncSetAttribute(conv1x1_kernel<true>,  cudaFuncAttributeMaxDynamicSharedMemorySize, 49152);
  cudaFuncSetAttribute(conv1x1_kernel<false>, cudaFuncAttributeMaxDynamicSharedMemorySize, 32768);
  cudaFuncSetAttribute(time_space_fused_kernel, cudaFuncAttributeMaxDynamicSharedMemorySize, SM_TOTAL);
  cudaFuncSetAttribute(space_score_kernel,      cudaFuncAttributeMaxDynamicSharedMemorySize, SM_TOTAL);

  static cudaStream_t s2 = 0;
  static cudaEvent_t evFork = 0, evJoin = 0;
  static bool tried = false;
  if (!tried) {
    tried = true;
    if (cudaStreamCreateWithFlags(&s2, cudaStreamNonBlocking) != cudaSuccess) s2 = 0;
    if (s2) {
      if (cudaEventCreateWithFlags(&evFork, cudaEventDisableTiming) != cudaSuccess ||
          cudaEventCreateWithFlags(&evJoin, cudaEventDisableTiming) != cudaSuccess) {
        s2 = 0;
      }
    }
  }

  if (s2) {
    cudaEventRecord(evFork, 0);
    cudaStreamWaitEvent(s2, evFork, 0);
    conv1x1_kernel<false><<<dim3(1024, 16), 256, 32768, s2>>>(assist, wk, bk, kh, kl,
                                                              (const float*)0, (const float*)0,
                                                              (__nv_bfloat16*)0, (__nv_bfloat16*)0);
    transpose_kernel<<<dim3(1024, 16), 256, 0, s2>>>(kh, kl, kth, ktl);
    cudaEventRecord(evJoin, s2);

    conv1x1_kernel<true><<<dim3(1024, 4), 256, 49152>>>(mainx, wq, bq, qh, ql, wv, bv, vh, vl);
    transpose_kernel<<<dim3(256, 16), 256>>>(qh, ql, qth, qtl);
    transpose_kernel<<<dim3(256, 16), 256>>>(vh, vl, vth, vtl);

    cudaStreamWaitEvent(0, evJoin, 0);
    space_score_kernel<<<dim3(4, 256), 256, SM_TOTAL>>>();
    time_space_fused_kernel<<<dim3(4, 256), 256, SM_TOTAL>>>(mainx, out);
  } else {
    conv1x1_kernel<true><<<dim3(1024, 4), 256, 49152>>>(mainx, wq, bq, qh, ql, wv, bv, vh, vl);
    conv1x1_kernel<false><<<dim3(1024, 16), 256, 32768>>>(assist, wk, bk, kh, kl,
                                                          (const float*)0, (const float*)0,
                                                          (__nv_bfloat16*)0, (__nv_bfloat16*)0);
    transpose_kernel<<<dim3(256, 16), 256>>>(qh, ql, qth, qtl);
    transpose_kernel<<<dim3(256, 16), 256>>>(vh, vl, vth, vtl);
    transpose_kernel<<<dim3(1024, 16), 256>>>(kh, kl, kth, ktl);
    space_score_kernel<<<dim3(4, 256), 256, SM_TOTAL>>>();
    time_space_fused_kernel<<<dim3(4, 256), 256, SM_TOTAL>>>(mainx, out);
  }
}

// round 17
// speedup vs baseline: 1.1517x; 1.0978x over previous
#include <cuda_runtime.h>
#include <cuda_bf16.h>
#include <cstdint>

static const int HWX = 65536;   // 256*256
static const int WD  = 256;
static const int CH  = 64;

// ---------------------------------------------------------------------------
// Scratch: everything pre-split into bf16 hi/lo, straight and transposed.
// ---------------------------------------------------------------------------
__device__ __nv_bfloat16 g_qh[16777216],  g_ql[16777216];
__device__ __nv_bfloat16 g_vh[16777216],  g_vl[16777216];
__device__ __nv_bfloat16 g_kh[67108864],  g_kl[67108864];
__device__ __nv_bfloat16 g_qth[16777216], g_qtl[16777216];
__device__ __nv_bfloat16 g_vth[16777216], g_vtl[16777216];
__device__ __nv_bfloat16 g_kth[67108864], g_ktl[67108864];
__device__ __nv_bfloat16 g_psh[16777216], g_psl[16777216];  // sum_n P_space, TRANSPOSED [v][w]

// ---------------------------------------------------------------------------
// SMEM layout (attention). PITCH 144 B per 64-k row -> conflict-free ldmatrix.
// ---------------------------------------------------------------------------
static const int PITCH   = 144;
static const int A_CHUNK = 64 * PITCH;              // 9216
static const int SM_AH   = 0;                       // 4*9216 = 36864
static const int SM_AL   = 36864;
static const int B_PLANE = 256 * PITCH;             // 36864
static const int SM_B0H  = 73728;
static const int SM_B0L  = SM_B0H + B_PLANE;        // 110592
static const int SM_B1H  = SM_B0L + B_PLANE;        // 147456
static const int SM_B1L  = SM_B1H + B_PLANE;        // 184320
static const int SM_RS   = SM_B1L + B_PLANE;        // 221184 ([4][64] floats)
static const int SM_TOTAL = SM_RS + 1024;           // 222208

// ---------------------------------------------------------------------------
// Helpers
// ---------------------------------------------------------------------------
__device__ __forceinline__ uint32_t smem_u32(const void* p) {
  uint32_t a;
  asm("{ .reg .u64 t; cvta.to.shared.u64 t, %1; cvt.u32.u64 %0, t; }" : "=r"(a) : "l"(p));
  return a;
}
__device__ __forceinline__ void split2(float x0, float x1, uint32_t& hi2, uint32_t& lo2) {
  __nv_bfloat162 h = __floats2bfloat162_rn(x0, x1);
  float r0 = x0 - __bfloat162float(h.x);
  float r1 = x1 - __bfloat162float(h.y);
  __nv_bfloat162 l = __floats2bfloat162_rn(r0, r1);
  hi2 = *(uint32_t*)&h;
  lo2 = *(uint32_t*)&l;
}
__device__ __forceinline__ void split1(float x, __nv_bfloat16& h, __nv_bfloat16& l) {
  h = __float2bfloat16(x);
  l = __float2bfloat16(x - __bfloat162float(h));
}

__device__ __forceinline__ void mma16816(float c[4], uint32_t a0, uint32_t a1,
                                         uint32_t a2, uint32_t a3,
                                         uint32_t b0, uint32_t b1) {
  asm volatile(
    "mma.sync.aligned.m16n8k16.row.col.f32.bf16.bf16.f32 "
    "{%0,%1,%2,%3}, {%4,%5,%6,%7}, {%8,%9}, {%0,%1,%2,%3};"
    : "+f"(c[0]), "+f"(c[1]), "+f"(c[2]), "+f"(c[3])
    : "r"(a0), "r"(a1), "r"(a2), "r"(a3), "r"(b0), "r"(b1));
}
__device__ __forceinline__ void ldmx4(uint32_t& r0, uint32_t& r1, uint32_t& r2, uint32_t& r3,
                                      uint32_t addr) {
  asm volatile("ldmatrix.sync.aligned.m8n8.x4.shared.b16 {%0,%1,%2,%3}, [%4];"
               : "=r"(r0), "=r"(r1), "=r"(r2), "=r"(r3) : "r"(addr));
}

#define CP16(dst, src)  asm volatile("cp.async.cg.shared.global [%0], [%1], 16;" :: "r"(dst), "l"(src))
#define CP_COMMIT()     asm volatile("cp.async.commit_group;" ::: "memory")
#define CP_WAIT0()      asm volatile("cp.async.wait_group 0;" ::: "memory")

// A fill (all 4 k-chunks, 64 rows): strength-reduced pointer-marching copies.
__device__ __forceinline__ void cpa_A(uint32_t sb, const __nv_bfloat16* srcH,
                                      const __nv_bfloat16* srcL, size_t rowbase, int tid) {
  const int m0 = tid >> 5, s = tid & 31;
  const __nv_bfloat16* pH = srcH + rowbase + (size_t)m0 * WD + s * 8;
  const __nv_bfloat16* pL = srcL + rowbase + (size_t)m0 * WD + s * 8;
  const uint32_t off = (uint32_t)((s >> 3) * A_CHUNK + m0 * PITCH + (s & 7) * 16);
  uint32_t dh = sb + SM_AH + off, dl = sb + SM_AL + off;
#pragma unroll
  for (int j = 0; j < 8; j++) {
    CP16(dh, pH);
    CP16(dl, pL);
    pH += 8 * WD; pL += 8 * WD;
    dh += 8 * PITCH; dl += 8 * PITCH;
  }
}
// B fill (one 64-k chunk, 256 rows)
__device__ __forceinline__ void cpa_B(uint32_t sb, uint32_t dH, uint32_t dL,
                                      const __nv_bfloat16* srcH, const __nv_bfloat16* srcL,
                                      size_t base, int koff, int tid) {
  const int n0 = tid >> 3, s = tid & 7;
  const __nv_bfloat16* pH = srcH + base + (size_t)n0 * WD + koff + s * 8;
  const __nv_bfloat16* pL = srcL + base + (size_t)n0 * WD + koff + s * 8;
  uint32_t dh = sb + dH + (uint32_t)(n0 * PITCH + s * 16);
  uint32_t dl = sb + dL + (uint32_t)(n0 * PITCH + s * 16);
#pragma unroll
  for (int j = 0; j < 8; j++) {
    CP16(dh, pH);
    CP16(dl, pL);
    pH += 32 * WD; pL += 32 * WD;
    dh += 32 * PITCH; dl += 32 * PITCH;
  }
}

// ---------------------------------------------------------------------------
// One 64-k chunk: acc[2][8][4] += A_chunk * B^T  (bf16 split)
// FULL=true : 3-term (hi*hi + lo*hi + hi*lo) — for ctx GEMMs.
// FULL=false: 2-term (hi*hi + lo*hi)         — for score GEMMs (pre-softmax;
//             dropping a_hi*b_lo costs ~2^-9 logit error, diluted by softmax).
// Warp tile 32(M) x 64(N): wm in {0,1}, wn in {0..3}. 8 warps.
// ---------------------------------------------------------------------------
template <bool FULL>
__device__ __forceinline__ void gemm_chunk(uint32_t sb, int ac, uint32_t bufH, uint32_t bufL,
                                           int lane, int wm, int wn, float (&acc)[2][8][4]) {
  const int i8 = lane & 7, q = lane >> 3;
  uint32_t bAddr = sb + (q < 2 ? bufH : bufL) + (uint32_t)(wn * 64 + i8) * PITCH + (q & 1) * 16;
  const int i16 = lane & 15, hsel = lane >> 4;
  uint32_t aAddrH = sb + SM_AH + ac * A_CHUNK + (uint32_t)(wm * 32 + i16) * PITCH + hsel * 16;
  uint32_t aAddrL = aAddrH + (SM_AL - SM_AH);
#pragma unroll
  for (int kt = 0; kt < 4; kt++) {
    uint32_t h00, h01, h02, h03, h10, h11, h12, h13;
    uint32_t l00, l01, l02, l03, l10, l11, l12, l13;
    ldmx4(h00, h01, h02, h03, aAddrH + kt * 32);
    ldmx4(h10, h11, h12, h13, aAddrH + 16 * PITCH + kt * 32);
    ldmx4(l00, l01, l02, l03, aAddrL + kt * 32);
    ldmx4(l10, l11, l12, l13, aAddrL + 16 * PITCH + kt * 32);
#pragma unroll
    for (int nt = 0; nt < 8; nt++) {
      uint32_t b0, b1, b2, b3;  // bh0, bh1, bl0, bl1 in ONE ldmatrix
      ldmx4(b0, b1, b2, b3, bAddr + nt * 8 * PITCH + kt * 32);
      mma16816(acc[0][nt], h00, h01, h02, h03, b0, b1);
      mma16816(acc[1][nt], h10, h11, h12, h13, b0, b1);
      mma16816(acc[0][nt], l00, l01, l02, l03, b0, b1);
      mma16816(acc[1][nt], l10, l11, l12, l13, b0, b1);
      if (FULL) {
        mma16816(acc[0][nt], h00, h01, h02, h03, b2, b3);
        mma16816(acc[1][nt], h10, h11, h12, h13, b2, b3);
      }
    }
  }
}

__device__ __forceinline__ void zero_acc(float (&a)[2][8][4]) {
#pragma unroll
  for (int mi = 0; mi < 2; mi++)
#pragma unroll
    for (int nt = 0; nt < 8; nt++)
#pragma unroll
      for (int e = 0; e < 4; e++) a[mi][nt][e] = 0.f;
}

// softmax over full 256-wide rows (cols span the 4 wn warps), accumulate into P
__device__ __forceinline__ void softmax_acc(char* smem, float (&S)[2][8][4], float (&P)[2][8][4],
                                            int lane, int wm, int wn) {
  const int r = lane >> 2, t = lane & 3;
  float* rs = (float*)(smem + SM_RS);  // [4 wn][64 rows]
  float s[4] = {0.f, 0.f, 0.f, 0.f};
#pragma unroll
  for (int mi = 0; mi < 2; mi++)
#pragma unroll
    for (int nt = 0; nt < 8; nt++) {
#pragma unroll
      for (int e = 0; e < 4; e++) S[mi][nt][e] = __expf(S[mi][nt][e] * 0.0625f);
      s[mi * 2 + 0] += S[mi][nt][0] + S[mi][nt][1];
      s[mi * 2 + 1] += S[mi][nt][2] + S[mi][nt][3];
    }
#pragma unroll
  for (int o = 1; o <= 2; o <<= 1)
#pragma unroll
    for (int i = 0; i < 4; i++) s[i] += __shfl_xor_sync(0xffffffffu, s[i], o);
  if (t == 0) {
#pragma unroll
    for (int mi = 0; mi < 2; mi++) {
      rs[wn * 64 + wm * 32 + mi * 16 + r]     = s[mi * 2 + 0];
      rs[wn * 64 + wm * 32 + mi * 16 + r + 8] = s[mi * 2 + 1];
    }
  }
  __syncthreads();
#pragma unroll
  for (int mi = 0; mi < 2; mi++) {
    int row = wm * 32 + mi * 16 + r;
    float inv0 = 1.0f / (rs[row] + rs[64 + row] + rs[128 + row] + rs[192 + row]);
    float inv1 = 1.0f / (rs[row + 8] + rs[64 + row + 8] + rs[128 + row + 8] + rs[192 + row + 8]);
#pragma unroll
    for (int nt = 0; nt < 8; nt++) {
      P[mi][nt][0] += S[mi][nt][0] * inv0;
      P[mi][nt][1] += S[mi][nt][1] * inv0;
      P[mi][nt][2] += S[mi][nt][2] * inv1;
      P[mi][nt][3] += S[mi][nt][3] * inv1;
    }
  }
  __syncthreads();
}

// write P fragments into the A smem region (split, fragment-native layout)
__device__ __forceinline__ void store_P_to_A(char* smem, const float (&P)[2][8][4],
                                             int lane, int wm, int wn) {
  const int r = lane >> 2, t = lane & 3;
#pragma unroll
  for (int mi = 0; mi < 2; mi++)
#pragma unroll
    for (int nt = 0; nt < 8; nt++) {
      int m = wm * 32 + mi * 16 + r;
      int koff = (nt * 8 + 2 * t) * 2;
      uint32_t hi, lo;
      split2(P[mi][nt][0], P[mi][nt][1], hi, lo);
      *(uint32_t*)(smem + SM_AH + wn * A_CHUNK + m * PITCH + koff) = hi;
      *(uint32_t*)(smem + SM_AL + wn * A_CHUNK + m * PITCH + koff) = lo;
      split2(P[mi][nt][2], P[mi][nt][3], hi, lo);
      *(uint32_t*)(smem + SM_AH + wn * A_CHUNK + (m + 8) * PITCH + koff) = hi;
      *(uint32_t*)(smem + SM_AL + wn * A_CHUNK + (m + 8) * PITCH + koff) = lo;
    }
}

// ---------------------------------------------------------------------------
// Kernel: time attention + space ctx fused. grid (4 h-blocks, 256 bc).
//   out = main + Pacc_t @ V + V @ P_s
// ---------------------------------------------------------------------------
__global__ __launch_bounds__(256, 1) void time_space_fused_kernel(
    const float* __restrict__ mainx, float* __restrict__ out)
{
  extern __shared__ char smem[];
  uint32_t sb = smem_u32(smem);
  const int tid = threadIdx.x, lane = tid & 31, wid = tid >> 5;
  const int wm = wid & 1, wn = wid >> 1;
  const int bc = blockIdx.y, h0 = blockIdx.x * 64;
  const size_t pb = (size_t)bc * HWX;

  float Pacc[2][8][4], Sacc[2][8][4];
  zero_acc(Pacc);

  // ---- time scores: A <- Q straight; B <- K stream (2-term split) ----
  cpa_A(sb, g_qh, g_ql, pb + (size_t)h0 * WD, tid);
  cpa_B(sb, SM_B0H, SM_B0L, g_kh, g_kl, pb, 0, tid);
  CP_COMMIT();

  for (int c = 0; c < 16; c++) {
    int kc = c & 3;
    CP_WAIT0();
    __syncthreads();
    if (c + 1 < 16) {
      size_t b1 = ((size_t)((c + 1) >> 2) * 256 + bc) * HWX;
      uint32_t dh = ((c + 1) & 1) ? SM_B1H : SM_B0H;
      uint32_t dl = ((c + 1) & 1) ? SM_B1L : SM_B0L;
      cpa_B(sb, dh, dl, g_kh, g_kl, b1, ((c + 1) & 3) * 64, tid);
      CP_COMMIT();
    }
    if (kc == 0) zero_acc(Sacc);
    gemm_chunk<false>(sb, kc, (c & 1) ? SM_B1H : SM_B0H, (c & 1) ? SM_B1L : SM_B0L, lane, wm, wn, Sacc);
    if (kc == 3) softmax_acc(smem, Sacc, Pacc, lane, wm, wn);
  }

  // ---- time ctx: A <- split(Pacc); B <- V^T stream; O_t in Sacc (3-term) ----
  store_P_to_A(smem, Pacc, lane, wm, wn);
  zero_acc(Sacc);
  __syncthreads();
  cpa_B(sb, SM_B0H, SM_B0L, g_vth, g_vtl, pb, 0, tid);
  CP_COMMIT();
  for (int kc = 0; kc < 4; kc++) {
    CP_WAIT0();
    __syncthreads();
    if (kc + 1 < 4) {
      uint32_t dh = ((kc + 1) & 1) ? SM_B1H : SM_B0H;
      uint32_t dl = ((kc + 1) & 1) ? SM_B1L : SM_B0L;
      cpa_B(sb, dh, dl, g_vth, g_vtl, pb, (kc + 1) * 64, tid);
      CP_COMMIT();
    }
    gemm_chunk<true>(sb, kc, (kc & 1) ? SM_B1H : SM_B0H, (kc & 1) ? SM_B1L : SM_B0L, lane, wm, wn, Sacc);
  }
  __syncthreads();   // all warps done reading A (P frags) before the V rewrite

  // ---- space ctx: A <- V straight; B <- psT stream; O_s in Pacc (3-term) ----
  zero_acc(Pacc);
  cpa_A(sb, g_vh, g_vl, pb + (size_t)h0 * WD, tid);
  cpa_B(sb, SM_B0H, SM_B0L, g_psh, g_psl, pb, 0, tid);
  CP_COMMIT();
  for (int kc = 0; kc < 4; kc++) {
    CP_WAIT0();
    __syncthreads();
    if (kc + 1 < 4) {
      uint32_t dh = ((kc + 1) & 1) ? SM_B1H : SM_B0H;
      uint32_t dl = ((kc + 1) & 1) ? SM_B1L : SM_B0L;
      cpa_B(sb, dh, dl, g_psh, g_psl, pb, (kc + 1) * 64, tid);
      CP_COMMIT();
    }
    gemm_chunk<true>(sb, kc, (kc & 1) ? SM_B1H : SM_B0H, (kc & 1) ? SM_B1L : SM_B0L, lane, wm, wn, Pacc);
  }

  // ---- single epilogue: out = main + O_t + O_s ----
  const float* mp = mainx + pb;
  float* op = out + pb;
  const int r = lane >> 2, t = lane & 3;
#pragma unroll
  for (int mi = 0; mi < 2; mi++)
#pragma unroll
    for (int nt = 0; nt < 8; nt++) {
      int row = h0 + wm * 32 + mi * 16 + r;
      int col = wn * 64 + nt * 8 + 2 * t;
      float2 m0 = *(const float2*)&mp[(size_t)row * WD + col];
      float2 m1 = *(const float2*)&mp[(size_t)(row + 8) * WD + col];
      *(float2*)&op[(size_t)row * WD + col] =
          make_float2(m0.x + Sacc[mi][nt][0] + Pacc[mi][nt][0],
                      m0.y + Sacc[mi][nt][1] + Pacc[mi][nt][1]);
      *(float2*)&op[(size_t)(row + 8) * WD + col] =
          make_float2(m1.x + Sacc[mi][nt][2] + Pacc[mi][nt][2],
                      m1.y + Sacc[mi][nt][3] + Pacc[mi][nt][3]);
    }
}

// ---------------------------------------------------------------------------
// Kernel: space scores -> psT (transposed, split). grid (4 w-blocks, 256 bc).
// 2-term split scores; psT staged in smem, coalesced 16B global writes.
// ---------------------------------------------------------------------------
__global__ __launch_bounds__(256, 1) void space_score_kernel()
{
  extern __shared__ char smem[];
  uint32_t sb = smem_u32(smem);
  const int tid = threadIdx.x, lane = tid & 31, wid = tid >> 5;
  const int wm = wid & 1, wn = wid >> 1;
  const int bc = blockIdx.y, w0 = blockIdx.x * 64;
  const size_t pb = (size_t)bc * HWX;

  float Pacc[2][8][4], Sacc[2][8][4];
  zero_acc(Pacc);

  cpa_A(sb, g_qth, g_qtl, pb + (size_t)w0 * WD, tid);
  cpa_B(sb, SM_B0H, SM_B0L, g_kth, g_ktl, pb, 0, tid);
  CP_COMMIT();

  for (int c = 0; c < 16; c++) {
    int kc = c & 3;
    CP_WAIT0();
    __syncthreads();
    if (c + 1 < 16) {
      size_t b1 = ((size_t)((c + 1) >> 2) * 256 + bc) * HWX;
      uint32_t dh = ((c + 1) & 1) ? SM_B1H : SM_B0H;
      uint32_t dl = ((c + 1) & 1) ? SM_B1L : SM_B0L;
      cpa_B(sb, dh, dl, g_kth, g_ktl, b1, ((c + 1) & 3) * 64, tid);
      CP_COMMIT();
    }
    if (kc == 0) zero_acc(Sacc);
    gemm_chunk<false>(sb, kc, (c & 1) ? SM_B1H : SM_B0H, (c & 1) ? SM_B1L : SM_B0L, lane, wm, wn, Sacc);
    if (kc == 3) softmax_acc(smem, Sacc, Pacc, lane, wm, wn);
  }

  // stage fragments into smem psT tile [256 v][64 w] (hi in B0H, lo in B0L)
  __syncthreads();
  {
    char* ph = smem + SM_B0H;
    char* pl = smem + SM_B0L;
    const int r = lane >> 2, t = lane & 3;
#pragma unroll
    for (int mi = 0; mi < 2; mi++)
#pragma unroll
      for (int nt = 0; nt < 8; nt++) {
        int wl = wm * 32 + mi * 16 + r;
        int v  = wn * 64 + nt * 8 + 2 * t;
        __nv_bfloat16 h, l;
        split1(Pacc[mi][nt][0], h, l);
        *(__nv_bfloat16*)(ph + v * PITCH + wl * 2) = h;
        *(__nv_bfloat16*)(pl + v * PITCH + wl * 2) = l;
        split1(Pacc[mi][nt][1], h, l);
        *(__nv_bfloat16*)(ph + (v + 1) * PITCH + wl * 2) = h;
        *(__nv_bfloat16*)(pl + (v + 1) * PITCH + wl * 2) = l;
        split1(Pacc[mi][nt][2], h, l);
        *(__nv_bfloat16*)(ph + v * PITCH + (wl + 8) * 2) = h;
        *(__nv_bfloat16*)(pl + v * PITCH + (wl + 8) * 2) = l;
        split1(Pacc[mi][nt][3], h, l);
        *(__nv_bfloat16*)(ph + (v + 1) * PITCH + (wl + 8) * 2) = h;
        *(__nv_bfloat16*)(pl + (v + 1) * PITCH + (wl + 8) * 2) = l;
      }
  }
  __syncthreads();
  // coalesced copy: 256 v rows x 64 w (128B = 8 x 16B) per plane
  for (int idx = tid; idx < 4096; idx += 256) {
    int plane = idx >> 11, rem = idx & 2047;
    int v = rem >> 3, s = rem & 7;
    uint4 val = *(uint4*)(smem + (plane ? SM_B0L : SM_B0H) + v * PITCH + s * 16);
    *(uint4*)((plane ? g_psl : g_psh) + pb + (size_t)v * WD + w0 + s * 8) = val;
  }
}

// ---------------------------------------------------------------------------
// conv1x1 (FFMA) -> bf16 hi/lo outputs (x1 or x2)
// ---------------------------------------------------------------------------
template <bool DUAL>
__global__ __launch_bounds__(256, 1) void conv1x1_kernel(
    const float* __restrict__ x,
    const float* __restrict__ w1, const float* __restrict__ b1,
    __nv_bfloat16* __restrict__ y1h, __nv_bfloat16* __restrict__ y1l,
    const float* __restrict__ w2, const float* __restrict__ b2,
    __nv_bfloat16* __restrict__ y2h, __nv_bfloat16* __restrict__ y2l)
{
  extern __shared__ float sm[];
  float* Xs  = sm;
  float* W1s = sm + 4096;
  float* W2s = sm + 8192;

  const int tid = threadIdx.x;
  const int pb  = blockIdx.y;
  const int px0 = blockIdx.x * 64;
  const float* xp = x + (size_t)pb * CH * HWX;

#pragma unroll 4
  for (int idx = tid; idx < 4096; idx += 256) {
    W1s[idx] = w1[idx];
    if (DUAL) W2s[idx] = w2[idx];
    Xs[idx] = xp[(size_t)(idx >> 6) * HWX + px0 + (idx & 63)];
  }
  __syncthreads();

  const int ocg = tid >> 4;
  const int pxg = tid & 15;
  float a1[4][4] = {};
  float a2[4][4] = {};

#pragma unroll 8
  for (int i = 0; i < 64; i++) {
    float4 xv = *(const float4*)&Xs[i * 64 + pxg * 4];
#pragma unroll
    for (int r = 0; r < 4; r++) {
      float wv = W1s[(ocg * 4 + r) * 64 + i];
      a1[r][0] += wv * xv.x; a1[r][1] += wv * xv.y;
      a1[r][2] += wv * xv.z; a1[r][3] += wv * xv.w;
      if (DUAL) {
        float w2v = W2s[(ocg * 4 + r) * 64 + i];
        a2[r][0] += w2v * xv.x; a2[r][1] += w2v * xv.y;
        a2[r][2] += w2v * xv.z; a2[r][3] += w2v * xv.w;
      }
    }
  }

#pragma unroll
  for (int r = 0; r < 4; r++) {
    int oc = ocg * 4 + r;
    size_t base = (size_t)pb * CH * HWX + (size_t)oc * HWX + px0 + pxg * 4;
    float bb = b1[oc];
    uint32_t h0, l0, h1, l1;
    split2(a1[r][0] + bb, a1[r][1] + bb, h0, l0);
    split2(a1[r][2] + bb, a1[r][3] + bb, h1, l1);
    *(uint2*)(y1h + base) = make_uint2(h0, h1);
    *(uint2*)(y1l + base) = make_uint2(l0, l1);
    if (DUAL) {
      float bb2 = b2[oc];
      split2(a2[r][0] + bb2, a2[r][1] + bb2, h0, l0);
      split2(a2[r][2] + bb2, a2[r][3] + bb2, h1, l1);
      *(uint2*)(y2h + base) = make_uint2(h0, h1);
      *(uint2*)(y2l + base) = make_uint2(l0, l1);
    }
  }
}

// ---------------------------------------------------------------------------
// packed transpose (R13-validated): dst[p][w*256+h] = src[p][h*256+w].
// 64x64 tiles, static smem, grid (planes, 16), occ ~86%.
// ---------------------------------------------------------------------------
__global__ __launch_bounds__(256, 1) void transpose_kernel(
    const __nv_bfloat16* __restrict__ srcH, const __nv_bfloat16* __restrict__ srcL,
    __nv_bfloat16* __restrict__ dstH, __nv_bfloat16* __restrict__ dstL)
{
  __shared__ uint32_t tile[2][64][33];
  const int p = blockIdx.x, tIdx = blockIdx.y;
  const int h0 = (tIdx >> 2) * 64, w0 = (tIdx & 3) * 64;
  const size_t base = (size_t)p * HWX;
  const int tid = threadIdx.x;

  for (int idx = tid; idx < 1024; idx += 256) {
    int plane = idx >> 9, rem = idx & 511;
    int hp = rem >> 4, w4 = rem & 15;
    const __nv_bfloat16* s = (plane ? srcL : srcH) + base + (size_t)(h0 + 2 * hp) * WD + w0 + w4 * 4;
    uint2 a = *(const uint2*)s;
    uint2 b = *(const uint2*)(s + WD);
    tile[plane][w4 * 4 + 0][hp] = __byte_perm(a.x, b.x, 0x5410);
    tile[plane][w4 * 4 + 1][hp] = __byte_perm(a.x, b.x, 0x7632);
    tile[plane][w4 * 4 + 2][hp] = __byte_perm(a.y, b.y, 0x5410);
    tile[plane][w4 * 4 + 3][hp] = __byte_perm(a.y, b.y, 0x7632);
  }
  __syncthreads();

  for (int idx = tid; idx < 1024; idx += 256) {
    int plane = idx >> 9, rem = idx & 511;
    int w = rem >> 3, oct = rem & 7;
    uint4 v;
    v.x = tile[plane][w][oct * 4 + 0];
    v.y = tile[plane][w][oct * 4 + 1];
    v.z = tile[plane][w][oct * 4 + 2];
    v.w = tile[plane][w][oct * 4 + 3];
    __nv_bfloat16* d = (plane ? dstL : dstH) + base + (size_t)(w0 + w) * WD + h0 + oct * 8;
    *(uint4*)d = v;
  }
}

// ---------------------------------------------------------------------------
extern "C" void kernel_launch(void* const* d_in, const int* in_sizes, int n_in,
                              void* d_out, int out_size)
{
  (void)in_sizes; (void)n_in; (void)out_size;
  const float* mainx  = (const float*)d_in[0];
  const float* assist = (const float*)d_in[1];
  const float* wq = (const float*)d_in[2];
  const float* bq = (const float*)d_in[3];
  const float* wk = (const float*)d_in[4];
  const float* bk = (const float*)d_in[5];
  const float* wv = (const float*)d_in[6];
  const float* bv = (const float*)d_in[7];
  float* out = (float*)d_out;

  __nv_bfloat16 *qh, *ql, *vh, *vl, *kh, *kl, *qth, *qtl, *vth, *vtl, *kth, *ktl;
  cudaGetSymbolAddress((void**)&qh,  g_qh);  cudaGetSymbolAddress((void**)&ql,  g_ql);
  cudaGetSymbolAddress((void**)&vh,  g_vh);  cudaGetSymbolAddress((void**)&vl,  g_vl);
  cudaGetSymbolAddress((void**)&kh,  g_kh);  cudaGetSymbolAddress((void**)&kl,  g_kl);
  cudaGetSymbolAddress((void**)&qth, g_qth); cudaGetSymbolAddress((void**)&qtl, g_qtl);
  cudaGetSymbolAddress((void**)&vth, g_vth); cudaGetSymbolAddress((void**)&vtl, g_vtl);
  cudaGetSymbolAddress((void**)&kth, g_kth); cudaGetSymbolAddress((void**)&ktl, g_ktl);

  cudaFuncSetAttribute(conv1x1_kernel<true>,  cudaFuncAttributeMaxDynamicSharedMemorySize, 49152);
  cudaFuncSetAttribute(conv1x1_kernel<false>, cudaFuncAttributeMaxDynamicSharedMemorySize, 32768);
  cudaFuncSetAttribute(time_space_fused_kernel, cudaFuncAttributeMaxDynamicSharedMemorySize, SM_TOTAL);
  cudaFuncSetAttribute(space_score_kernel,      cudaFuncAttributeMaxDynamicSharedMemorySize, SM_TOTAL);

  static cudaStream_t s2 = 0;
  static cudaEvent_t evFork = 0, evJoin = 0;
  static bool tried = false;
  if (!tried) {
    tried = true;
    if (cudaStreamCreateWithFlags(&s2, cudaStreamNonBlocking) != cudaSuccess) s2 = 0;
    if (s2) {
      if (cudaEventCreateWithFlags(&evFork, cudaEventDisableTiming) != cudaSuccess ||
          cudaEventCreateWithFlags(&evJoin, cudaEventDisableTiming) != cudaSuccess) {
        s2 = 0;
      }
    }
  }

  if (s2) {
    cudaEventRecord(evFork, 0);
    cudaStreamWaitEvent(s2, evFork, 0);
    conv1x1_kernel<false><<<dim3(1024, 16), 256, 32768, s2>>>(assist, wk, bk, kh, kl,
                                                              (const float*)0, (const float*)0,
                                                              (__nv_bfloat16*)0, (__nv_bfloat16*)0);
    transpose_kernel<<<dim3(1024, 16), 256, 0, s2>>>(kh, kl, kth, ktl);
    cudaEventRecord(evJoin, s2);

    conv1x1_kernel<true><<<dim3(1024, 4), 256, 49152>>>(mainx, wq, bq, qh, ql, wv, bv, vh, vl);
    transpose_kernel<<<dim3(256, 16), 256>>>(qh, ql, qth, qtl);
    transpose_kernel<<<dim3(256, 16), 256>>>(vh, vl, vth, vtl);

    cudaStreamWaitEvent(0, evJoin, 0);
    space_score_kernel<<<dim3(4, 256), 256, SM_TOTAL>>>();
    time_space_fused_kernel<<<dim3(4, 256), 256, SM_TOTAL>>>(mainx, out);
  } else {
    conv1x1_kernel<true><<<dim3(1024, 4), 256, 49152>>>(mainx, wq, bq, qh, ql, wv, bv, vh, vl);
    conv1x1_kernel<false><<<dim3(1024, 16), 256, 32768>>>(assist, wk, bk, kh, kl,
                                                          (const float*)0, (const float*)0,
                                                          (__nv_bfloat16*)0, (__nv_bfloat16*)0);
    transpose_kernel<<<dim3(256, 16), 256>>>(qh, ql, qth, qtl);
    transpose_kernel<<<dim3(256, 16), 256>>>(vh, vl, vth, vtl);
    transpose_kernel<<<dim3(1024, 16), 256>>>(kh, kl, kth, ktl);
    space_score_kernel<<<dim3(4, 256), 256, SM_TOTAL>>>();
    time_space_fused_kernel<<<dim3(4, 256), 256, SM_TOTAL>>>(mainx, out);
  }
}